// round 16
// baseline (speedup 1.0000x reference)
#include <cuda_runtime.h>

// FWHT (11 stages, N=2048) + sign flip on last quarter, batch 16384.
// ONE ROW PER 64-THREAD BLOCK (one warp pair). 32 fp32/thread.
// Swap-shuffles for lane bits, one smem half-exchange for bit 10.
// L2 policy split: input loads carry an L2::evict_last cache hint (input is
// re-read every graph replay and nearly fits the 126MB L2), output uses
// streaming evict-first stores (__stcs) — write-once data must not evict it.
//
// Bits: i0,i1=k0,k1 ; i2..i6=lane ; i7,i8,i9=k2,k3,k4 ; i10=warp.
//   1) radix-4 on k0,k1            (register-local)
//   2) butterflies on k2,k3,k4     (register-local)
//   3) 5 swap-shuffle stages for lane bits (1 SHFL per register pair)
//   4) STS scrambled->linear (padded), __syncthreads,
//      LDS both halves + bit-10 butterfly + sign/scale + STG.128 (.cs).

__global__ void __launch_bounds__(64, 16)
fwht_sign_kernel8(const float* __restrict__ in, float* __restrict__ out) {
    __shared__ float sbuf[2][1056];          // 2 halves x (1024 + 32 pad)

    const int half = threadIdx.x >> 5;       // index bit 10
    const int lane = threadIdx.x & 31;
    const int row  = blockIdx.x;

    const float4* __restrict__ src =
        reinterpret_cast<const float4*>(in) + (size_t)row * 512 + half * 256;

    // L2 retention policy for the input stream.
    unsigned long long pol;
    asm("createpolicy.fractional.L2::evict_last.b64 %0, 1.0;" : "=l"(pol));

    // Coalesced load: 8 x LDG.128 with L2::evict_last hint.
    float v[32];
    #pragma unroll
    for (int r = 0; r < 8; r++) {
        float x, y, z, w;
        asm("ld.global.nc.L2::cache_hint.v4.f32 {%0,%1,%2,%3}, [%4], %5;"
            : "=f"(x), "=f"(y), "=f"(z), "=f"(w)
            : "l"(src + r * 32 + lane), "l"(pol));
        v[4*r+0] = x; v[4*r+1] = y; v[4*r+2] = z; v[4*r+3] = w;
    }

    // Bits 0,1: radix-4 inside each float4.
    #pragma unroll
    for (int q = 0; q < 32; q += 4) {
        float a0 = v[q+0], a1 = v[q+1], a2 = v[q+2], a3 = v[q+3];
        float b0 = a0 + a1, b1 = a0 - a1, b2 = a2 + a3, b3 = a2 - a3;
        v[q+0] = b0 + b2;
        v[q+1] = b1 + b3;
        v[q+2] = b0 - b2;
        v[q+3] = b1 - b3;
    }

    // Bits 7,8,9: register-local butterflies (register bits k2,k3,k4).
    #pragma unroll
    for (int m = 4; m <= 16; m <<= 1) {
        #pragma unroll
        for (int k = 0; k < 32; k++) {
            if (k & m) continue;
            float a = v[k], b = v[k|m];
            v[k]   = a + b;
            v[k|m] = a - b;
        }
    }

    // Bits 2..6: swap-shuffle stages (1 SHFL per register pair).
    #pragma unroll
    for (int s = 0; s < 5; s++) {
        const int  h  = 1 << s;
        const bool up = (lane & h) != 0;
        #pragma unroll
        for (int k = 0; k < 32; k++) {
            if (k & h) continue;
            const int ko = k | h;
            float send = up ? v[k] : v[ko];
            float t = __shfl_xor_sync(0xffffffffu, send, h);
            float a = up ? t     : v[k];
            float b = up ? v[ko] : t;
            v[k]  = a + b;
            v[ko] = a - b;
        }
    }

    // Publish own half to smem, undoing the scramble (padded, conflict-free).
    // idx = (lane&3) | (k<<2) | ((lane>>2)<<7); addr = idx + 4*(idx>>7).
    {
        float* sb = sbuf[half];
        const int base = (lane & 3) + (lane >> 2) * 132;
        #pragma unroll
        for (int k = 0; k < 32; k++)
            sb[base + 4 * k] = v[k];
    }

    __syncthreads();   // 2 warps only

    // Bit-10 butterfly + sign + scale + streaming coalesced store.
    {
        const float* slo = sbuf[0];
        const float* shi = sbuf[1];
        float4* dst = reinterpret_cast<float4*>(out) + (size_t)row * 512 + half * 256;
        const float S = 0.022097086912079612f;   // (1/sqrt(2))^11

        #pragma unroll
        for (int g = 0; g < 8; g++) {
            const int a = g * 132 + lane * 4;    // conflict-free LDS.128
            float4 lo = *reinterpret_cast<const float4*>(slo + a);
            float4 hi = *reinterpret_cast<const float4*>(shi + a);
            const float s = (half == 1 && g >= 4) ? -S : S;
            float4 o;
            if (half == 0) {
                o.x = (lo.x + hi.x) * s; o.y = (lo.y + hi.y) * s;
                o.z = (lo.z + hi.z) * s; o.w = (lo.w + hi.w) * s;
            } else {
                o.x = (lo.x - hi.x) * s; o.y = (lo.y - hi.y) * s;
                o.z = (lo.z - hi.z) * s; o.w = (lo.w - hi.w) * s;
            }
            __stcs(&dst[g * 32 + lane], o);      // evict-first: protect resident input
        }
    }
}

extern "C" void kernel_launch(void* const* d_in, const int* in_sizes, int n_in,
                              void* d_out, int out_size) {
    const float* x = (const float*)d_in[0];
    float* out = (float*)d_out;
    const int rows = in_sizes[0] / 2048;     // 16384
    fwht_sign_kernel8<<<rows, 64>>>(x, out);
}

// round 17
// speedup vs baseline: 1.0015x; 1.0015x over previous
#include <cuda_runtime.h>

// FWHT (11 stages, N=2048) + sign flip on last quarter, batch 16384.
// ONE ROW PER 64-THREAD BLOCK (one warp pair), 32 fp32/thread, k = c + 4r.
//
// Initial bits: i0,i1=k0,k1 ; i2..i6=L0..L4 ; i7,i8,i9=r0,r1,r2 ; i10=warp.
// Stage schedule (minimal MIO):
//   A) radix-4 on i0,i1                    (register-local)
//   B) butterflies i7,i8,i9                (register-local)
//   C) THREE swap-shuffle stages: (i2: L0<->k2), (i3: L1<->k3), (i4: L2<->k4)
//      -> post-swap layout is CONTIGUOUS in k:
//         idx = k + 32*L3 + 64*L4 + 128*L0 + 256*L1 + 512*L2
//   D) 8x STS.128 contiguous (padded +4 floats per 128-group, conflict-free)
//   E) __syncthreads (2 warps)
//   F) radix-8 over i5(L3-dim), i6(L4-dim), i10(buffer) read straight from
//      smem, fused with scale (1/sqrt2)^11 and the last-quarter sign
//      (negative iff i10==1 && i9==1 <=> half==1 && R2==1), 8x STG.128 (.cs).

__device__ __forceinline__ float4 add4(float4 a, float4 b) {
    return make_float4(a.x + b.x, a.y + b.y, a.z + b.z, a.w + b.w);
}
__device__ __forceinline__ float4 sub4(float4 a, float4 b) {
    return make_float4(a.x - b.x, a.y - b.y, a.z - b.z, a.w - b.w);
}
// (a + sh*b) * s
__device__ __forceinline__ float4 comb4(float4 a, float4 b, float sh, float s) {
    return make_float4((a.x + sh * b.x) * s, (a.y + sh * b.y) * s,
                       (a.z + sh * b.z) * s, (a.w + sh * b.w) * s);
}

__global__ void __launch_bounds__(64, 16)
fwht_sign_kernel9(const float* __restrict__ in, float* __restrict__ out) {
    __shared__ float sbuf[2][1056];          // 2 halves x (1024 + 32 pad)

    const int half = threadIdx.x >> 5;       // index bit 10
    const int lane = threadIdx.x & 31;
    const int row  = blockIdx.x;

    const float4* __restrict__ src =
        reinterpret_cast<const float4*>(in) + (size_t)row * 512 + half * 256;

    // Coalesced load: 8 x LDG.128.
    float v[32];
    #pragma unroll
    for (int r = 0; r < 8; r++) {
        float4 f = src[r * 32 + lane];
        v[4*r+0] = f.x; v[4*r+1] = f.y; v[4*r+2] = f.z; v[4*r+3] = f.w;
    }

    // A) Bits i0,i1: radix-4 inside each float4.
    #pragma unroll
    for (int q = 0; q < 32; q += 4) {
        float a0 = v[q+0], a1 = v[q+1], a2 = v[q+2], a3 = v[q+3];
        float b0 = a0 + a1, b1 = a0 - a1, b2 = a2 + a3, b3 = a2 - a3;
        v[q+0] = b0 + b2;
        v[q+1] = b1 + b3;
        v[q+2] = b0 - b2;
        v[q+3] = b1 - b3;
    }

    // B) Bits i7,i8,i9: register-local butterflies (k-bits 4,8,16).
    #pragma unroll
    for (int m = 4; m <= 16; m <<= 1) {
        #pragma unroll
        for (int k = 0; k < 32; k++) {
            if (k & m) continue;
            float a = v[k], b = v[k|m];
            v[k]   = a + b;
            v[k|m] = a - b;
        }
    }

    // C) Bits i2,i3,i4: swap-shuffle with r-bit partners (h=1,2,4 ; m=4,8,16).
    #pragma unroll
    for (int s = 0; s < 3; s++) {
        const int  h  = 1 << s;
        const int  m  = 4 << s;
        const bool up = (lane & h) != 0;
        #pragma unroll
        for (int k = 0; k < 32; k++) {
            if (k & m) continue;
            const int ko = k | m;
            float send = up ? v[k] : v[ko];
            float t = __shfl_xor_sync(0xffffffffu, send, h);
            float a = up ? t     : v[k];
            float b = up ? v[ko] : t;
            v[k]  = a + b;
            v[ko] = a - b;
        }
    }

    // D) Contiguous STS.128: thread owns idx = k + 32*L3 + 64*L4 + 128*L0
    //    + 256*L1 + 512*L2 ; pad = +4 floats per 128-float group.
    {
        const int L0 = lane & 1, L1 = (lane >> 1) & 1, L2 = (lane >> 2) & 1;
        const int L3 = (lane >> 3) & 1, L4 = (lane >> 4) & 1;
        const int pb = 32*L3 + 64*L4 + 128*L0 + 256*L1 + 512*L2
                     + 4*(L0 + 2*L1 + 4*L2);
        float* sb = sbuf[half];
        #pragma unroll
        for (int g = 0; g < 8; g++)
            *reinterpret_cast<float4*>(sb + pb + 4*g) =
                make_float4(v[4*g+0], v[4*g+1], v[4*g+2], v[4*g+3]);
    }

    __syncthreads();   // 2 warps only

    // F) Radix-8 over (i5, i6, i10) + sign/scale + coalesced streaming store.
    //    Output bits: o0,1=c ; o2,3,4=L0,L1,L2 ; o5=R0 ; o6=R1 ; o7=L3 ;
    //    o8=L4 ; o9=R2 ; o10=half.
    {
        const int L3 = (lane >> 3) & 1, L4 = (lane >> 4) & 1;
        const int A    = 4*(lane & 7) + 128*L3 + 256*L4;  // lane part (floats)
        const int padL = 4*(L3 + 2*L4);
        const float S  = 0.022097086912079612f;           // (1/sqrt(2))^11
        const float sh = (half == 0) ? 1.0f : -1.0f;      // i10 butterfly sign
        const float* s0 = sbuf[0];
        const float* s1 = sbuf[1];
        float4* dst = reinterpret_cast<float4*>(out) + (size_t)row * 512;
        const int of4 = (A >> 2) + 256 * half;            // float4 units

        #pragma unroll
        for (int R2 = 0; R2 < 2; R2++) {
            const int baseIn = A + padL + R2 * 528;       // 512 + 16 pad
            // F[buf][b], b = beta0 + 2*beta1 ; input offset +32*b0 +64*b1.
            float4 F0[4], F1[4];
            #pragma unroll
            for (int b = 0; b < 4; b++) {
                const int off = baseIn + 32*(b & 1) + 64*(b >> 1);
                F0[b] = *reinterpret_cast<const float4*>(s0 + off);
                F1[b] = *reinterpret_cast<const float4*>(s1 + off);
            }
            const float s = (half == 1 && R2 == 1) ? -S : S;

            // beta0 stage, then beta1 stage (per buffer).
            float4 P0a = add4(F0[0], F0[1]), M0a = sub4(F0[0], F0[1]);
            float4 P1a = add4(F0[2], F0[3]), M1a = sub4(F0[2], F0[3]);
            float4 X00a = add4(P0a, P1a), X01a = sub4(P0a, P1a);
            float4 X10a = add4(M0a, M1a), X11a = sub4(M0a, M1a);

            float4 P0b = add4(F1[0], F1[1]), M0b = sub4(F1[0], F1[1]);
            float4 P1b = add4(F1[2], F1[3]), M1b = sub4(F1[2], F1[3]);
            float4 X00b = add4(P0b, P1b), X01b = sub4(P0b, P1b);
            float4 X10b = add4(M0b, M1b), X11b = sub4(M0b, M1b);

            // i10 stage + scale; store at o = A + 32*R0 + 64*R1 + 512*R2 (+half).
            const int ob = of4 + 128 * R2;
            __stcs(&dst[ob +  0], comb4(X00a, X00b, sh, s));   // R0=0,R1=0
            __stcs(&dst[ob +  8], comb4(X10a, X10b, sh, s));   // R0=1,R1=0
            __stcs(&dst[ob + 16], comb4(X01a, X01b, sh, s));   // R0=0,R1=1
            __stcs(&dst[ob + 24], comb4(X11a, X11b, sh, s));   // R0=1,R1=1
        }
    }
}

extern "C" void kernel_launch(void* const* d_in, const int* in_sizes, int n_in,
                              void* d_out, int out_size) {
    const float* x = (const float*)d_in[0];
    float* out = (float*)d_out;
    const int rows = in_sizes[0] / 2048;     // 16384
    fwht_sign_kernel9<<<rows, 64>>>(x, out);
}